// round 6
// baseline (speedup 1.0000x reference)
#include <cuda_runtime.h>
#include <cuda_bf16.h>
#include <cstdint>

#define T_LEN     131072
#define N_ST      256
#define RING_ROWS 40     // 5 chunks x 8 rows = 40KB smem ring
#define CHUNK     8
#define PREF_ROWS 32     // prefill 4 chunks; max 4 pending cp.async groups
#define FLT_MIN_N 1.17549435e-38f

// Scratch: per-step branch costs, cost[t][s] = -log(probs[t][s]). 128 MB.
static __device__ float g_cost[T_LEN * N_ST];

// ---------------------------------------------------------------------------
// Phase A: parallel likelihoods. One warp per time sample t.
// Lane owns strided states s = lane + 32k; shfl.down 16..1 tree, lane-0 S.
// KEY FIX (R6): XLA-GPU compiles f32 with FTZ=1. Emulate it at the two spots
// where subnormals arise: (1) expf underflow (a < -87.34) -> p flushed to 0
// (reference cost = +inf; without the flush we get finite cost ~88-104 — a
// large inf-vs-finite topology difference, invariant to every ULP-level
// change, matching the bit-identical rel_err of rounds 1-5), (2) q = p/S
// division output subnormal -> 0.
// ---------------------------------------------------------------------------
__global__ void __launch_bounds__(256) va_cost_kernel(const float* __restrict__ rx,
                                                      const float* __restrict__ h,
                                                      float* __restrict__ out) {
    __shared__ float sp[N_ST];
    __shared__ float hs[8];
    const int tid = threadIdx.x;
    if (tid < 8) hs[tid] = h[tid];
    __syncthreads();
    {   // sp[s] = sum_j (1-2*bit_j(s)) * h[j], bits MSB-first, ascending j
        float acc = 0.0f;
#pragma unroll
        for (int j = 0; j < 8; ++j) {
            float sym = ((tid >> (7 - j)) & 1) ? -1.0f : 1.0f;
            acc += sym * hs[j];
        }
        sp[tid] = acc;
    }
    __syncthreads();

    const int lane = tid & 31;
    const int t    = blockIdx.x * 8 + (tid >> 5);
    const float r  = rx[t];

    float p[8];
    float acc = 0.0f;
#pragma unroll
    for (int k = 0; k < 8; ++k) {
        float d = r - sp[lane + 32 * k];
        float a = (-(d * d)) / 0.2f;        // IEEE div.rn, 2*sigma2 = 0.2
        float e = expf(a);                  // libdevice __nv_expf
        p[k] = (e < FLT_MIN_N) ? 0.0f : e;  // FTZ: flush subnormal exp result
        acc += p[k];
    }
#pragma unroll
    for (int off = 16; off > 0; off >>= 1)
        acc += __shfl_down_sync(0xffffffffu, acc, off);
    const float S = __shfl_sync(0xffffffffu, acc, 0);

    float bv = -1.0f; int bi = 0;
#pragma unroll
    for (int k = 0; k < 8; ++k) {
        float q = __fdiv_rn(p[k], S);
        q = (q < FLT_MIN_N) ? 0.0f : q;     // FTZ: flush subnormal quotient
        int s = lane + 32 * k;
        if (q > bv) { bv = q; bi = s; }
        g_cost[t * N_ST + s] = -logf(q);    // q=0 -> -(-inf) = +inf
    }
#pragma unroll
    for (int off = 16; off > 0; off >>= 1) {
        float ov = __shfl_xor_sync(0xffffffffu, bv, off);
        int   oi = __shfl_xor_sync(0xffffffffu, bi, off);
        if (ov > bv || (ov == bv && oi < bi)) { bv = ov; bi = oi; }
    }

    if (lane == 0) {
        out[T_LEN + t]     = (float)(bi & 1);   // confident_bits
        out[2 * T_LEN + t] = bv;                // confidence_word
    }
}

// ---------------------------------------------------------------------------
// Phase B: serial trellis. tt[i] == tt[i+128] -> 128-periodic metrics,
// 4 per lane in one warp. new_u[4L+r] = min(v[8L+2r], v[8L+2r+1]),
// v[j] = u[j mod 128] + cost[j]. bit_t = argmin(u_t)%2 before update,
// first-index ties. Ring: 5 chunks of 8 rows; one wait_group(3) + one
// commit_group per 8 steps -> max 4 pending async groups.
// ---------------------------------------------------------------------------
__global__ void __launch_bounds__(32) va_viterbi_kernel(float* __restrict__ out) {
    __shared__ float4 ring[RING_ROWS * 64];   // 40 rows x 256 floats = 40KB
    const int lane = threadIdx.x;
    const unsigned smem_base = (unsigned)__cvta_generic_to_shared(ring);

    for (int c = 0; c < 4; ++c) {
#pragma unroll
        for (int r = 0; r < CHUNK; ++r) {
            int row = c * CHUNK + r;
            unsigned dst = smem_base + (unsigned)((row * 64 + lane * 2) * 16);
            const float* src = &g_cost[(size_t)row * N_ST + lane * 8];
            asm volatile("cp.async.cg.shared.global [%0], [%1], 16;\n"
                         "cp.async.cg.shared.global [%2], [%3], 16;\n"
                         :: "r"(dst), "l"(src), "r"(dst + 16u), "l"(src + 4) : "memory");
        }
        asm volatile("cp.async.commit_group;" ::: "memory");
    }

    float u0 = 0.0f, u1 = 0.0f, u2 = 0.0f, u3 = 0.0f;
    const int src0 = (2 * lane) & 31;
    const int src1 = (2 * lane + 1) & 31;
    const int base_li = 4 * lane;
    int slot_c = 0;            // consume slot (row t -> slot t % 40)
    int slot_p = PREF_ROWS;    // produce slot (row t+32 -> slot (t+32) % 40)

    for (int t = 0; t < T_LEN; t += 8) {
        asm volatile("cp.async.wait_group 3;" ::: "memory");
#pragma unroll
        for (int k = 0; k < 8; ++k) {
            const float4* cptr = &ring[slot_c * 64 + lane * 2];
            float4 ca = cptr[0];
            float4 cb = cptr[1];

            // bit = argmin(u) % 2, first-index ties (off critical path);
            // u >= +0 always -> uint order == float order (inf = 0x7f800000 ok)
            float lv = u0; int li = base_li;
            if (u1 < lv) { lv = u1; li = base_li + 1; }
            if (u2 < lv) { lv = u2; li = base_li + 2; }
            if (u3 < lv) { lv = u3; li = base_li + 3; }
            unsigned lb = __float_as_uint(lv);
            unsigned mv, idx;
            asm volatile("redux.sync.min.u32 %0, %1, 0xffffffff;" : "=r"(mv) : "r"(lb));
            unsigned cand = (lb == mv) ? (unsigned)li : 0xffffffffu;
            asm volatile("redux.sync.min.u32 %0, %1, 0xffffffff;" : "=r"(idx) : "r"(cand));
            if (lane == 0) out[t + k] = (float)(idx & 1u);

            // trellis update (critical path: SHFL -> FADD -> FMNMX)
            float a0 = __shfl_sync(0xffffffffu, u0, src0);
            float a1 = __shfl_sync(0xffffffffu, u1, src0);
            float a2 = __shfl_sync(0xffffffffu, u2, src0);
            float a3 = __shfl_sync(0xffffffffu, u3, src0);
            float b0 = __shfl_sync(0xffffffffu, u0, src1);
            float b1 = __shfl_sync(0xffffffffu, u1, src1);
            float b2 = __shfl_sync(0xffffffffu, u2, src1);
            float b3 = __shfl_sync(0xffffffffu, u3, src1);
            u0 = fminf(a0 + ca.x, a1 + ca.y);
            u1 = fminf(a2 + ca.z, a3 + ca.w);
            u2 = fminf(b0 + cb.x, b1 + cb.y);
            u3 = fminf(b2 + cb.z, b3 + cb.w);

            int tp = t + k + PREF_ROWS;
            if (tp < T_LEN) {
                unsigned dst = smem_base + (unsigned)((slot_p * 64 + lane * 2) * 16);
                const float* srcp = &g_cost[(size_t)tp * N_ST + lane * 8];
                asm volatile("cp.async.cg.shared.global [%0], [%1], 16;\n"
                             "cp.async.cg.shared.global [%2], [%3], 16;\n"
                             :: "r"(dst), "l"(srcp), "r"(dst + 16u), "l"(srcp + 4) : "memory");
            }
            if (++slot_c == RING_ROWS) slot_c = 0;
            if (++slot_p == RING_ROWS) slot_p = 0;
        }
        asm volatile("cp.async.commit_group;" ::: "memory");
    }
}

// ---------------------------------------------------------------------------
// out layout = [detected(T) | confident_bits(T) | confidence(T)], f32.
// ---------------------------------------------------------------------------
extern "C" void kernel_launch(void* const* d_in, const int* in_sizes, int n_in,
                              void* d_out, int out_size) {
    const float* rx = (const float*)d_in[0];
    const float* h  = (const float*)d_in[1];
    if (n_in >= 2 && in_sizes[0] == 8) {   // defensive: inputs swapped
        rx = (const float*)d_in[1];
        h  = (const float*)d_in[0];
    }
    float* out = (float*)d_out;
    va_cost_kernel<<<T_LEN / 8, 256>>>(rx, h, out);
    va_viterbi_kernel<<<1, 32>>>(out);
}